// round 16
// baseline (speedup 1.0000x reference)
#include <cuda_runtime.h>
#include <cuda_fp16.h>
#include <math.h>
#include <stdint.h>

// ---------------------------------------------------------------------------
// Problem constants
// ---------------------------------------------------------------------------
#define BATCH    2
#define SEQ      2048
#define DMODEL   2048
#define NHEADS   16
#define NKV      4
#define HDIM     128
#define M_TOK    (BATCH*SEQ)           // 4096
#define KVDIM    (NKV*2*HDIM)          // 1024
#define NQKV     (DMODEL + KVDIM)      // 3072

// ---------------------------------------------------------------------------
// Scratch
// ---------------------------------------------------------------------------
__device__ __half g_in_h  [M_TOK*DMODEL];
__device__ __half g_wqkv_h[NQKV*DMODEL];     // transposed [N,K]
__device__ __half g_wo_h  [DMODEL*DMODEL];   // transposed [N,K]
__device__ __half g_x_h   [M_TOK*DMODEL];    // attention out, fp16
__device__ __half g_q [BATCH*NHEADS*SEQ*HDIM];  // fp16 [B,H,S,D]
__device__ __half g_k [BATCH*NKV*SEQ*HDIM];     // fp16 [B,KV,S,D]
__device__ __half g_vt[BATCH*NKV*HDIM*SEQ];     // fp16 [B,KV,D,S]
__device__ float2 g_rope[SEQ*64];               // (sin, cos) per (pos, freq)

// ---------------------------------------------------------------------------
// Helpers
// ---------------------------------------------------------------------------
__device__ __forceinline__ void mma_f16(float c[4], const uint32_t a[4], const uint32_t b[2]) {
    asm volatile(
        "mma.sync.aligned.m16n8k16.row.col.f32.f16.f16.f32 "
        "{%0,%1,%2,%3},{%4,%5,%6,%7},{%8,%9},{%0,%1,%2,%3};"
        : "+f"(c[0]), "+f"(c[1]), "+f"(c[2]), "+f"(c[3])
        : "r"(a[0]), "r"(a[1]), "r"(a[2]), "r"(a[3]), "r"(b[0]), "r"(b[1]));
}

__device__ __forceinline__ void ldsm_x4(uint32_t r[4], uint32_t saddr) {
    asm volatile("ldmatrix.sync.aligned.m8n8.x4.shared.b16 {%0,%1,%2,%3}, [%4];"
        : "=r"(r[0]), "=r"(r[1]), "=r"(r[2]), "=r"(r[3]) : "r"(saddr));
}

__device__ __forceinline__ void cpa16(void* smem, const void* g) {
    uint32_t s = (uint32_t)__cvta_generic_to_shared(smem);
    asm volatile("cp.async.cg.shared.global [%0], [%1], 16;\n" :: "r"(s), "l"(g));
}
__device__ __forceinline__ void cp_commit() { asm volatile("cp.async.commit_group;"); }
__device__ __forceinline__ void cp_wait1()  { asm volatile("cp.async.wait_group 1;"); }
__device__ __forceinline__ void cp_wait0()  { asm volatile("cp.async.wait_group 0;"); }

__device__ __forceinline__ uint32_t packh2(float a, float b) {
    __half2 h = __floats2half2_rn(a, b);
    return *(uint32_t*)&h;
}

// ---------------------------------------------------------------------------
// Merged staging kernel (coalesced transpose32)
// ---------------------------------------------------------------------------
#define STG_CVT   8192
#define STG_WQ    (STG_CVT + 4096)
#define STG_WKV   (STG_WQ + 2048)
#define STG_WO    (STG_WKV + 4096)
#define STG_TOT   (STG_WO + 512)

__device__ __forceinline__ void transpose32(const float* __restrict__ W,
                                            __half* __restrict__ T,
                                            int K, int N, int n0, int k0,
                                            int tid, float (*t)[33])
{
    int tx = tid & 31, ty = tid >> 5;
    #pragma unroll
    for (int i = 0; i < 4; i++)
        t[ty + 8*i][tx] = W[(size_t)(k0 + ty + 8*i)*N + n0 + tx];
    __syncthreads();
    #pragma unroll
    for (int i = 0; i < 4; i++)
        T[(size_t)(n0 + ty + 8*i)*K + k0 + tx] = __float2half_rn(t[tx][ty + 8*i]);
}

__global__ void staging(const float4* __restrict__ inputs,
                        const float* __restrict__ wq,
                        const float* __restrict__ wkv,
                        const float* __restrict__ wo,
                        __half2* __restrict__ in_h,
                        __half* __restrict__ wqkv_h,
                        __half* __restrict__ wo_h,
                        float2* __restrict__ rope)
{
    __shared__ float t[32][33];
    const int bid = blockIdx.x, tid = threadIdx.x;

    if (bid < STG_CVT) {
        int i = bid*256 + tid;
        float4 x = inputs[i];
        in_h[2*i]   = __floats2half2_rn(x.x, x.y);
        in_h[2*i+1] = __floats2half2_rn(x.z, x.w);
    } else if (bid < STG_WQ) {
        int b = bid - STG_CVT;
        transpose32(wq, wqkv_h, DMODEL, DMODEL, (b & 63)*32, (b >> 6)*32, tid, t);
    } else if (bid < STG_WKV) {
        int b = bid - STG_WQ;
        transpose32(wkv, wqkv_h + (size_t)DMODEL*DMODEL, DMODEL, KVDIM,
                    (b & 31)*32, (b >> 5)*32, tid, t);
    } else if (bid < STG_WO) {
        int b = bid - STG_WKV;
        transpose32(wo, wo_h, DMODEL, DMODEL, (b & 63)*32, (b >> 6)*32, tid, t);
    } else {
        int idx = (bid - STG_WO)*256 + tid;
        int p = idx >> 6, i = idx & 63;
        float frac = (float)(2*i) * (1.0f/128.0f);
        float ts   = powf(10000.0f, frac);
        float sv, cv; sincosf((float)p / ts, &sv, &cv);
        rope[idx] = make_float2(sv, cv);
    }
}

// ---------------------------------------------------------------------------
// GEMM tile params (128x128x64, 256 thr = 8 warps (2x4), 2 CTA/SM)
// ---------------------------------------------------------------------------
#define HSTR 72
#define HBUF 18432
#define TSTR 132

#define GEMM_MAINLOOP()                                                          \
    const uint32_t sb0 = (uint32_t)__cvta_generic_to_shared(sh);                 \
    const int rowA = (lane & 7) + ((lane >> 3) & 1)*8;                           \
    const int colA = (lane >> 4)*8;                                              \
    const int rowB = (lane & 7) + ((lane >> 4) << 3);                            \
    const int colB = ((lane >> 3) & 1)*8;                                        \
    const uint32_t aOff = ((wr*64 + rowA)*HSTR + colA)*2;                        \
    const uint32_t bOff = (128*HSTR + (wc*32 + rowB)*HSTR + colB)*2;             \
    auto load_tile = [&](int buf, int k0) {                                      \
        __half* sA = sh + buf*HBUF;                                              \
        __half* sB = sA + 128*HSTR;                                              \
        _Pragma("unroll")                                                        \
        for (int i = 0; i < 4; i++) {                                            \
            int slot = tid + i*256;                                              \
            int r = slot >> 3, c8 = (slot & 7)*8;                                \
            cpa16(sA + r*HSTR + c8, A + (size_t)(bm + r)*K + k0 + c8);           \
            cpa16(sB + r*HSTR + c8, B + (size_t)(bn + r)*K + k0 + c8);           \
        }                                                                        \
        cp_commit();                                                             \
    };                                                                           \
    load_tile(0, 0);                                                             \
    const int KT = K / 64;                                                       \
    int buf = 0;                                                                 \
    for (int it = 0; it < KT; it++) {                                            \
        if (it + 1 < KT) { load_tile(buf ^ 1, (it + 1)*64); cp_wait1(); }        \
        else             { cp_wait0(); }                                         \
        __syncthreads();                                                         \
        const uint32_t aBase = sb0 + buf*HBUF*2 + aOff;                          \
        const uint32_t bBase = sb0 + buf*HBUF*2 + bOff;                          \
        _Pragma("unroll")                                                        \
        for (int ks = 0; ks < 4; ks++) {                                         \
            uint32_t a[4][4], bp0[4], bp1[4];                                    \
            _Pragma("unroll")                                                    \
            for (int mt = 0; mt < 4; mt++)                                       \
                ldsm_x4(a[mt], aBase + (mt*16*HSTR + ks*16)*2);                  \
            ldsm_x4(bp0, bBase + ks*16*2);                                       \
            ldsm_x4(bp1, bBase + (16*HSTR + ks*16)*2);                           \
            _Pragma("unroll")                                                    \
            for (int mt = 0; mt < 4; mt++) {                                     \
                mma_f16(acc[mt][0], a[mt], bp0);                                 \
                mma_f16(acc[mt][1], a[mt], bp0 + 2);                             \
                mma_f16(acc[mt][2], a[mt], bp1);                                 \
                mma_f16(acc[mt][3], a[mt], bp1 + 2);                             \
            }                                                                    \
        }                                                                        \
        __syncthreads();                                                         \
        buf ^= 1;                                                                \
    }

// ---------------------------------------------------------------------------
// Fused QKV projection + rope Q/K (table) + transpose V
// ---------------------------------------------------------------------------
__global__ __launch_bounds__(256, 2) void gemm_qkv(
    const __half* __restrict__ A, const __half* __restrict__ B,
    const float* __restrict__ bq, const float* __restrict__ bkv,
    const int* __restrict__ seq_pos, const float2* __restrict__ rope,
    __half* __restrict__ Qo, __half* __restrict__ Ko, __half* __restrict__ Vt)
{
    extern __shared__ __half sh[];
    const int tid  = threadIdx.x;
    const int lane = tid & 31, wid = tid >> 5;
    const int wr   = wid >> 2, wc = wid & 3;
    const int gr   = lane >> 2, qd = lane & 3;
    const int bm   = blockIdx.y*128, bn = blockIdx.x*128;
    const int K    = DMODEL;

    float acc[4][4][4];
    #pragma unroll
    for (int i = 0; i < 4; i++)
        #pragma unroll
        for (int j = 0; j < 4; j++)
            #pragma unroll
            for (int r = 0; r < 4; r++) acc[i][j][r] = 0.f;

    GEMM_MAINLOOP()

    float* tile = (float*)sh;
    const float* bias = (bn < DMODEL) ? (bq + bn) : (bkv + bn - DMODEL);
    #pragma unroll
    for (int nt = 0; nt < 4; nt++) {
        int col = wc*32 + nt*8 + 2*qd;
        float2 bv = *(const float2*)(bias + col);
        #pragma unroll
        for (int mt = 0; mt < 4; mt++) {
            int r = wr*64 + mt*16 + gr;
            tile[(r  )*TSTR + col]     = acc[mt][nt][0] + bv.x;
            tile[(r  )*TSTR + col + 1] = acc[mt][nt][1] + bv.y;
            tile[(r+8)*TSTR + col]     = acc[mt][nt][2] + bv.x;
            tile[(r+8)*TSTR + col + 1] = acc[mt][nt][3] + bv.y;
        }
    }
    __syncthreads();

    const int bb    = bm >> 11;
    const int sbase = bm & 2047;

    if (bn < DMODEL) {
        const int h = bn >> 7;
        __half* dst = Qo + ((size_t)(bb*NHEADS + h))*SEQ*HDIM;
        const float scale = 0.08838834764831845f;    // 1/sqrt(128)
        for (int r = wid; r < 128; r += 8) {
            int s = sbase + r;
            int pos = seq_pos[bb*SEQ + s];
            __half* d = dst + (size_t)s*HDIM;
            #pragma unroll
            for (int ii = 0; ii < 2; ii++) {
                int i = lane + ii*32;
                float2 sc = rope[pos*64 + i];
                float x1 = tile[r*TSTR + i], x2 = tile[r*TSTR + i + 64];
                d[i]      = __float2half_rn((x1*sc.y - x2*sc.x) * scale);
                d[i + 64] = __float2half_rn((x2*sc.y + x1*sc.x) * scale);
            }
        }
    } else {
        const int off = bn - DMODEL;
        const int kv  = off >> 8;
        if (((off >> 7) & 1) == 0) {
            __half* dst = Ko + ((size_t)(bb*NKV + kv))*SEQ*HDIM;
            for (int r = wid; r < 128; r += 8) {
                int s = sbase + r;
                int pos = seq_pos[bb*SEQ + s];
                __half* d = dst + (size_t)s*HDIM;
                #pragma unroll
                for (int ii = 0; ii < 2; ii++) {
                    int i = lane + ii*32;
                    float2 sc = rope[pos*64 + i];
                    float x1 = tile[r*TSTR + i], x2 = tile[r*TSTR + i + 64];
                    d[i]      = __float2half_rn(x1*sc.y - x2*sc.x);
                    d[i + 64] = __float2half_rn(x2*sc.y + x1*sc.x);
                }
            }
        } else {
            __half* dst = Vt + ((size_t)(bb*NKV + kv))*HDIM*SEQ;
            #pragma unroll
            for (int ci = 0; ci < 16; ci++) {
                int c = wid*16 + ci;
                __half* dc = dst + (size_t)c*SEQ + sbase;
                #pragma unroll
                for (int rr = 0; rr < 4; rr++) {
                    int r = lane + rr*32;
                    dc[r] = __float2half_rn(tile[r*TSTR + c]);
                }
            }
        }
    }
}

// ---------------------------------------------------------------------------
// O-projection GEMM
// ---------------------------------------------------------------------------
__global__ __launch_bounds__(256, 2) void gemm_f16(
    const __half* __restrict__ A, const __half* __restrict__ B,
    const float* __restrict__ bias, float* __restrict__ C,
    int M, int N, int K)
{
    extern __shared__ __half sh[];
    const int tid  = threadIdx.x;
    const int lane = tid & 31, wid = tid >> 5;
    const int wr   = wid >> 2, wc = wid & 3;
    const int gr   = lane >> 2, qd = lane & 3;
    const int bm   = blockIdx.y*128, bn = blockIdx.x*128;

    float acc[4][4][4];
    #pragma unroll
    for (int i = 0; i < 4; i++)
        #pragma unroll
        for (int j = 0; j < 4; j++)
            #pragma unroll
            for (int r = 0; r < 4; r++) acc[i][j][r] = 0.f;

    GEMM_MAINLOOP()

    #pragma unroll
    for (int nt = 0; nt < 4; nt++) {
        int col = bn + wc*32 + nt*8 + 2*qd;
        float2 bv = *(const float2*)(bias + col);
        #pragma unroll
        for (int mt = 0; mt < 4; mt++) {
            int row = bm + wr*64 + mt*16 + gr;
            *(float2*)(C + (size_t)row*N + col) =
                make_float2(acc[mt][nt][0] + bv.x, acc[mt][nt][1] + bv.y);
            *(float2*)(C + (size_t)(row + 8)*N + col) =
                make_float2(acc[mt][nt][2] + bv.x, acc[mt][nt][3] + bv.y);
        }
    }
}

// ---------------------------------------------------------------------------
// Flash attention: 128 thr = 4 warps, warp owns 16 rows; Q/P in regs;
// K/V fragment loads via ldmatrix; occ 3.
// ---------------------------------------------------------------------------
#define QS 136
#define VS 72
#define SMH_K0  0
#define SMH_K1  (64*QS)
#define SMH_V0  (2*64*QS)
#define SMH_V1  (2*64*QS + 128*VS)
#define FLASH_SMEM ((2*64*QS + 2*128*VS)*2)   // 71680 B

__global__ __launch_bounds__(128, 3) void flash_f16(
    const __half* __restrict__ Q, const __half* __restrict__ Kg,
    const __half* __restrict__ Vtg, __half* __restrict__ X)
{
    extern __shared__ __half smh[];

    const int qt  = 31 - blockIdx.x;
    const int h   = blockIdx.y;
    const int b   = blockIdx.z;
    const int kvh = h >> 2;
    const int q0  = qt * 64;

    const int tid  = threadIdx.x;
    const int lane = tid & 31, wid = tid >> 5;
    const int gr   = lane >> 2, qd = lane & 3;
    const int r0   = wid*16 + gr, r1 = r0 + 8;

    const __half* qb  = Q   + ((size_t)(b*NHEADS + h)*SEQ + q0)*HDIM;
    const __half* kb  = Kg  + (size_t)(b*NKV + kvh)*SEQ*HDIM;
    const __half* vtb = Vtg + (size_t)(b*NKV + kvh)*HDIM*SEQ;

    const uint32_t smb = (uint32_t)__cvta_generic_to_shared(smh);
    const int rowF = (lane & 7) + ((lane >> 4) << 3);
    const int colF = ((lane >> 3) & 1)*8;

    uint32_t qa[8][4];
    #pragma unroll
    for (int ks = 0; ks < 8; ks++) {
        qa[ks][0] = *(const uint32_t*)(qb + (size_t)r0*HDIM + ks*16     + 2*qd);
        qa[ks][1] = *(const uint32_t*)(qb + (size_t)r1*HDIM + ks*16     + 2*qd);
        qa[ks][2] = *(const uint32_t*)(qb + (size_t)r0*HDIM + ks*16 + 8 + 2*qd);
        qa[ks][3] = *(const uint32_t*)(qb + (size_t)r1*HDIM + ks*16 + 8 + 2*qd);
    }

    auto load_kv = [&](int buf, int kt) {
        __half* Ks = smh + (buf ? SMH_K1 : SMH_K0);
        __half* Vs = smh + (buf ? SMH_V1 : SMH_V0);
        const __half* kp = kb + (size_t)kt*64*HDIM;
        #pragma unroll
        for (int i = 0; i < 8; i++) {
            int slot = tid + i*128;
            int r = slot >> 4, c8 = (slot & 15)*8;
            cpa16(Ks + r*QS + c8, kp + r*HDIM + c8);
        }
        #pragma unroll
        for (int i = 0; i < 8; i++) {
            int slot = tid + i*128;
            int d = slot >> 3, c8 = (slot & 7)*8;
            cpa16(Vs + d*VS + c8, vtb + (size_t)d*SEQ + kt*64 + c8);
        }
        cp_commit();
    };

    load_kv(0, 0);

    float o[16][4];
    #pragma unroll
    for (int i = 0; i < 16; i++)
        #pragma unroll
        for (int j = 0; j < 4; j++) o[i][j] = 0.f;
    float m0 = -INFINITY, m1 = -INFINITY, l0 = 0.f, l1 = 0.f;

    for (int kt = 0; kt <= qt; kt++) {
        const int buf = kt & 1;
        __syncthreads();
        if (kt < qt) { load_kv(buf ^ 1, kt + 1); cp_wait1(); }
        else         { cp_wait0(); }
        __syncthreads();

        const uint32_t kBase = smb + ((buf ? SMH_K1 : SMH_K0) + rowF*QS + colF)*2;
        const uint32_t vBase = smb + ((buf ? SMH_V1 : SMH_V0) + rowF*VS + colF)*2;

        float s[8][4];
        #pragma unroll
        for (int nt = 0; nt < 8; nt++)
            #pragma unroll
            for (int j = 0; j < 4; j++) s[nt][j] = 0.f;

        #pragma unroll
        for (int ks = 0; ks < 8; ks++) {
            #pragma unroll
            for (int p = 0; p < 4; p++) {
                uint32_t bf[4];
                ldsm_x4(bf, kBase + (p*16*QS + ks*16)*2);
                mma_f16(s[2*p],     qa[ks], bf);
                mma_f16(s[2*p + 1], qa[ks], bf + 2);
            }
        }

        if (kt == qt) {
            #pragma unroll
            for (int nt = 0; nt < 8; nt++) {
                int cg = kt*64 + nt*8 + 2*qd;
                if (cg     > q0 + r0) s[nt][0] = -1e30f;
                if (cg + 1 > q0 + r0) s[nt][1] = -1e30f;
                if (cg     > q0 + r1) s[nt][2] = -1e30f;
                if (cg + 1 > q0 + r1) s[nt][3] = -1e30f;
            }
        }

        float mx0 = -INFINITY, mx1 = -INFINITY;
        #pragma unroll
        for (int nt = 0; nt < 8; nt++) {
            mx0 = fmaxf(mx0, fmaxf(s[nt][0], s[nt][1]));
            mx1 = fmaxf(mx1, fmaxf(s[nt][2], s[nt][3]));
        }
        mx0 = fmaxf(mx0, __shfl_xor_sync(0xffffffffu, mx0, 1));
        mx0 = fmaxf(mx0, __shfl_xor_sync(0xffffffffu, mx0, 2));
        mx1 = fmaxf(mx1, __shfl_xor_sync(0xffffffffu, mx1, 1));
        mx1 = fmaxf(mx1, __shfl_xor_sync(0xffffffffu, mx1, 2));
        float nm0 = fmaxf(m0, mx0), nm1 = fmaxf(m1, mx1);
        float corr0 = __expf(m0 - nm0), corr1 = __expf(m1 - nm1);

        uint32_t ph[8], pl[8];
        float sum0 = 0.f, sum1 = 0.f;
        #pragma unroll
        for (int nt = 0; nt < 8; nt++) {
            float p00 = __expf(s[nt][0] - nm0);
            float p01 = __expf(s[nt][1] - nm0);
            float p10 = __expf(s[nt][2] - nm1);
            float p11 = __expf(s[nt][3] - nm1);
            sum0 += p00 + p01; sum1 += p10 + p11;
            ph[nt] = packh2(p00, p01);
            pl[nt] = packh2(p10, p11);
        }
        sum0 += __shfl_xor_sync(0xffffffffu, sum0, 1);
        sum0 += __shfl_xor_sync(0xffffffffu, sum0, 2);
        sum1 += __shfl_xor_sync(0xffffffffu, sum1, 1);
        sum1 += __shfl_xor_sync(0xffffffffu, sum1, 2);
        l0 = l0*corr0 + sum0;
        l1 = l1*corr1 + sum1;
        m0 = nm0; m1 = nm1;

        #pragma unroll
        for (int nt = 0; nt < 16; nt++) {
            o[nt][0] *= corr0; o[nt][1] *= corr0;
            o[nt][2] *= corr1; o[nt][3] *= corr1;
        }

        #pragma unroll
        for (int t = 0; t < 4; t++) {
            uint32_t a[4] = { ph[2*t], pl[2*t], ph[2*t + 1], pl[2*t + 1] };
            #pragma unroll
            for (int p = 0; p < 8; p++) {
                uint32_t bf[4];
                ldsm_x4(bf, vBase + (p*16*VS + t*16)*2);
                mma_f16(o[2*p],     a, bf);
                mma_f16(o[2*p + 1], a, bf + 2);
            }
        }
    }

    float inv0 = 1.f / l0, inv1 = 1.f / l1;
    size_t rb0 = ((size_t)(b*SEQ + q0 + r0))*DMODEL + h*HDIM;
    size_t rb1 = ((size_t)(b*SEQ + q0 + r1))*DMODEL + h*HDIM;
    #pragma unroll
    for (int nt = 0; nt < 16; nt++) {
        int cc = nt*8 + 2*qd;
        *(__half2*)(X + rb0 + cc) = __floats2half2_rn(o[nt][0]*inv0, o[nt][1]*inv0);
        *(__half2*)(X + rb1 + cc) = __floats2half2_rn(o[nt][2]*inv1, o[nt][3]*inv1);
    }
}

// ---------------------------------------------------------------------------
// Launch
// ---------------------------------------------------------------------------
extern "C" void kernel_launch(void* const* d_in, const int* in_sizes, int n_in,
                              void* d_out, int out_size)
{
    const float* inputs  = (const float*)d_in[0];
    const int*   seq_pos = (const int*)  d_in[1];
    const float* wq      = (const float*)d_in[2];
    const float* bq      = (const float*)d_in[3];
    const float* wkv     = (const float*)d_in[4];
    const float* bkv     = (const float*)d_in[5];
    const float* wo      = (const float*)d_in[6];
    const float* bo      = (const float*)d_in[7];
    float* out = (float*)d_out;

    __half *in_h, *wqkv_h, *wo_h, *x_h, *q, *k, *vt;
    float2* rope;
    cudaGetSymbolAddress((void**)&in_h,   g_in_h);
    cudaGetSymbolAddress((void**)&wqkv_h, g_wqkv_h);
    cudaGetSymbolAddress((void**)&wo_h,   g_wo_h);
    cudaGetSymbolAddress((void**)&x_h,    g_x_h);
    cudaGetSymbolAddress((void**)&q,      g_q);
    cudaGetSymbolAddress((void**)&k,      g_k);
    cudaGetSymbolAddress((void**)&vt,     g_vt);
    cudaGetSymbolAddress((void**)&rope,   g_rope);

    const int GEMM_SMEM = 2*HBUF*2;     // 73728 B
    cudaFuncSetAttribute(gemm_qkv,
                         cudaFuncAttributeMaxDynamicSharedMemorySize, GEMM_SMEM);
    cudaFuncSetAttribute(gemm_f16,
                         cudaFuncAttributeMaxDynamicSharedMemorySize, GEMM_SMEM);
    cudaFuncSetAttribute(flash_f16,
                         cudaFuncAttributeMaxDynamicSharedMemorySize, FLASH_SMEM);

    // 0) merged staging
    staging<<<STG_TOT, 256>>>((const float4*)inputs, wq, wkv, wo,
                              (__half2*)in_h, wqkv_h, wo_h, rope);

    // 1) fused QKV projection + rope + V transpose
    gemm_qkv<<<dim3(NQKV/128, M_TOK/128), 256, GEMM_SMEM>>>(
        in_h, wqkv_h, bq, bkv, seq_pos, rope, q, k, vt);

    // 2) flash attention
    flash_f16<<<dim3(SEQ/64, NHEADS, BATCH), 128, FLASH_SMEM>>>(q, k, vt, x_h);

    // 3) output projection
    gemm_f16<<<dim3(DMODEL/128, M_TOK/128), 256, GEMM_SMEM>>>(
        x_h, wo_h, bo, out, M_TOK, DMODEL, DMODEL);
}

// round 17
// speedup vs baseline: 1.0058x; 1.0058x over previous
#include <cuda_runtime.h>
#include <cuda_fp16.h>
#include <math.h>
#include <stdint.h>

// ---------------------------------------------------------------------------
// Problem constants
// ---------------------------------------------------------------------------
#define BATCH    2
#define SEQ      2048
#define DMODEL   2048
#define NHEADS   16
#define NKV      4
#define HDIM     128
#define M_TOK    (BATCH*SEQ)           // 4096
#define KVDIM    (NKV*2*HDIM)          // 1024
#define NQKV     (DMODEL + KVDIM)      // 3072

// ---------------------------------------------------------------------------
// Scratch
// ---------------------------------------------------------------------------
__device__ __half g_in_h  [M_TOK*DMODEL];
__device__ __half g_wqkv_h[NQKV*DMODEL];     // transposed [N,K]
__device__ __half g_wo_h  [DMODEL*DMODEL];   // transposed [N,K]
__device__ __half g_x_h   [M_TOK*DMODEL];    // attention out, fp16
__device__ __half g_q [BATCH*NHEADS*SEQ*HDIM];  // fp16 [B,H,S,D]
__device__ __half g_k [BATCH*NKV*SEQ*HDIM];     // fp16 [B,KV,S,D]
__device__ __half g_vt[BATCH*NKV*HDIM*SEQ];     // fp16 [B,KV,D,S]
__device__ float2 g_rope[SEQ*64];               // (sin, cos) per (pos, freq)

// ---------------------------------------------------------------------------
// Helpers
// ---------------------------------------------------------------------------
__device__ __forceinline__ void mma_f16(float c[4], const uint32_t a[4], const uint32_t b[2]) {
    asm volatile(
        "mma.sync.aligned.m16n8k16.row.col.f32.f16.f16.f32 "
        "{%0,%1,%2,%3},{%4,%5,%6,%7},{%8,%9},{%0,%1,%2,%3};"
        : "+f"(c[0]), "+f"(c[1]), "+f"(c[2]), "+f"(c[3])
        : "r"(a[0]), "r"(a[1]), "r"(a[2]), "r"(a[3]), "r"(b[0]), "r"(b[1]));
}

__device__ __forceinline__ void ldsm_x4(uint32_t r[4], uint32_t saddr) {
    asm volatile("ldmatrix.sync.aligned.m8n8.x4.shared.b16 {%0,%1,%2,%3}, [%4];"
        : "=r"(r[0]), "=r"(r[1]), "=r"(r[2]), "=r"(r[3]) : "r"(saddr));
}

__device__ __forceinline__ void cpa16(void* smem, const void* g) {
    uint32_t s = (uint32_t)__cvta_generic_to_shared(smem);
    asm volatile("cp.async.cg.shared.global [%0], [%1], 16;\n" :: "r"(s), "l"(g));
}
__device__ __forceinline__ void cp_commit() { asm volatile("cp.async.commit_group;"); }
__device__ __forceinline__ void cp_wait1()  { asm volatile("cp.async.wait_group 1;"); }
__device__ __forceinline__ void cp_wait0()  { asm volatile("cp.async.wait_group 0;"); }

__device__ __forceinline__ uint32_t packh2(float a, float b) {
    __half2 h = __floats2half2_rn(a, b);
    return *(uint32_t*)&h;
}

// ---------------------------------------------------------------------------
// Merged staging kernel (cvt region: 32B in -> one 16B store per thread)
// ---------------------------------------------------------------------------
#define STG_CVT   4096
#define STG_WQ    (STG_CVT + 4096)
#define STG_WKV   (STG_WQ + 2048)
#define STG_WO    (STG_WKV + 4096)
#define STG_TOT   (STG_WO + 512)

__device__ __forceinline__ void transpose32(const float* __restrict__ W,
                                            __half* __restrict__ T,
                                            int K, int N, int n0, int k0,
                                            int tid, float (*t)[33])
{
    int tx = tid & 31, ty = tid >> 5;
    #pragma unroll
    for (int i = 0; i < 4; i++)
        t[ty + 8*i][tx] = W[(size_t)(k0 + ty + 8*i)*N + n0 + tx];
    __syncthreads();
    #pragma unroll
    for (int i = 0; i < 4; i++)
        T[(size_t)(n0 + ty + 8*i)*K + k0 + tx] = __float2half_rn(t[tx][ty + 8*i]);
}

__global__ void staging(const float4* __restrict__ inputs,
                        const float* __restrict__ wq,
                        const float* __restrict__ wkv,
                        const float* __restrict__ wo,
                        uint4* __restrict__ in_h,
                        __half* __restrict__ wqkv_h,
                        __half* __restrict__ wo_h,
                        float2* __restrict__ rope)
{
    __shared__ float t[32][33];
    const int bid = blockIdx.x, tid = threadIdx.x;

    if (bid < STG_CVT) {
        int i = bid*256 + tid;            // one uint4 (8 halves) per thread
        float4 x0 = inputs[2*i];
        float4 x1 = inputs[2*i + 1];
        uint4 o;
        o.x = packh2(x0.x, x0.y);
        o.y = packh2(x0.z, x0.w);
        o.z = packh2(x1.x, x1.y);
        o.w = packh2(x1.z, x1.w);
        in_h[i] = o;
    } else if (bid < STG_WQ) {
        int b = bid - STG_CVT;
        transpose32(wq, wqkv_h, DMODEL, DMODEL, (b & 63)*32, (b >> 6)*32, tid, t);
    } else if (bid < STG_WKV) {
        int b = bid - STG_WQ;
        transpose32(wkv, wqkv_h + (size_t)DMODEL*DMODEL, DMODEL, KVDIM,
                    (b & 31)*32, (b >> 5)*32, tid, t);
    } else if (bid < STG_WO) {
        int b = bid - STG_WKV;
        transpose32(wo, wo_h, DMODEL, DMODEL, (b & 63)*32, (b >> 6)*32, tid, t);
    } else {
        int idx = (bid - STG_WO)*256 + tid;
        int p = idx >> 6, i = idx & 63;
        float frac = (float)(2*i) * (1.0f/128.0f);
        float ts   = powf(10000.0f, frac);
        float sv, cv; sincosf((float)p / ts, &sv, &cv);
        rope[idx] = make_float2(sv, cv);
    }
}

// ---------------------------------------------------------------------------
// GEMM tile params (128x128x64, 256 thr = 8 warps (2x4), 2 CTA/SM)
// ---------------------------------------------------------------------------
#define HSTR 72
#define HBUF 18432
#define TSTR 132

#define GEMM_MAINLOOP()                                                          \
    const uint32_t sb0 = (uint32_t)__cvta_generic_to_shared(sh);                 \
    const int rowA = (lane & 7) + ((lane >> 3) & 1)*8;                           \
    const int colA = (lane >> 4)*8;                                              \
    const int rowB = (lane & 7) + ((lane >> 4) << 3);                            \
    const int colB = ((lane >> 3) & 1)*8;                                        \
    const uint32_t aOff = ((wr*64 + rowA)*HSTR + colA)*2;                        \
    const uint32_t bOff = (128*HSTR + (wc*32 + rowB)*HSTR + colB)*2;             \
    auto load_tile = [&](int buf, int k0) {                                      \
        __half* sA = sh + buf*HBUF;                                              \
        __half* sB = sA + 128*HSTR;                                              \
        _Pragma("unroll")                                                        \
        for (int i = 0; i < 4; i++) {                                            \
            int slot = tid + i*256;                                              \
            int r = slot >> 3, c8 = (slot & 7)*8;                                \
            cpa16(sA + r*HSTR + c8, A + (size_t)(bm + r)*K + k0 + c8);           \
            cpa16(sB + r*HSTR + c8, B + (size_t)(bn + r)*K + k0 + c8);           \
        }                                                                        \
        cp_commit();                                                             \
    };                                                                           \
    load_tile(0, 0);                                                             \
    const int KT = K / 64;                                                       \
    int buf = 0;                                                                 \
    for (int it = 0; it < KT; it++) {                                            \
        if (it + 1 < KT) { load_tile(buf ^ 1, (it + 1)*64); cp_wait1(); }        \
        else             { cp_wait0(); }                                         \
        __syncthreads();                                                         \
        const uint32_t aBase = sb0 + buf*HBUF*2 + aOff;                          \
        const uint32_t bBase = sb0 + buf*HBUF*2 + bOff;                          \
        _Pragma("unroll")                                                        \
        for (int ks = 0; ks < 4; ks++) {                                         \
            uint32_t a[4][4], bp0[4], bp1[4];                                    \
            _Pragma("unroll")                                                    \
            for (int mt = 0; mt < 4; mt++)                                       \
                ldsm_x4(a[mt], aBase + (mt*16*HSTR + ks*16)*2);                  \
            ldsm_x4(bp0, bBase + ks*16*2);                                       \
            ldsm_x4(bp1, bBase + (16*HSTR + ks*16)*2);                           \
            _Pragma("unroll")                                                    \
            for (int mt = 0; mt < 4; mt++) {                                     \
                mma_f16(acc[mt][0], a[mt], bp0);                                 \
                mma_f16(acc[mt][1], a[mt], bp0 + 2);                             \
                mma_f16(acc[mt][2], a[mt], bp1);                                 \
                mma_f16(acc[mt][3], a[mt], bp1 + 2);                             \
            }                                                                    \
        }                                                                        \
        __syncthreads();                                                         \
        buf ^= 1;                                                                \
    }

// ---------------------------------------------------------------------------
// Fused QKV projection + rope Q/K (table) + transpose V
// ---------------------------------------------------------------------------
__global__ __launch_bounds__(256, 2) void gemm_qkv(
    const __half* __restrict__ A, const __half* __restrict__ B,
    const float* __restrict__ bq, const float* __restrict__ bkv,
    const int* __restrict__ seq_pos, const float2* __restrict__ rope,
    __half* __restrict__ Qo, __half* __restrict__ Ko, __half* __restrict__ Vt)
{
    extern __shared__ __half sh[];
    const int tid  = threadIdx.x;
    const int lane = tid & 31, wid = tid >> 5;
    const int wr   = wid >> 2, wc = wid & 3;
    const int gr   = lane >> 2, qd = lane & 3;
    const int bm   = blockIdx.y*128, bn = blockIdx.x*128;
    const int K    = DMODEL;

    float acc[4][4][4];
    #pragma unroll
    for (int i = 0; i < 4; i++)
        #pragma unroll
        for (int j = 0; j < 4; j++)
            #pragma unroll
            for (int r = 0; r < 4; r++) acc[i][j][r] = 0.f;

    GEMM_MAINLOOP()

    float* tile = (float*)sh;
    const float* bias = (bn < DMODEL) ? (bq + bn) : (bkv + bn - DMODEL);
    #pragma unroll
    for (int nt = 0; nt < 4; nt++) {
        int col = wc*32 + nt*8 + 2*qd;
        float2 bv = *(const float2*)(bias + col);
        #pragma unroll
        for (int mt = 0; mt < 4; mt++) {
            int r = wr*64 + mt*16 + gr;
            tile[(r  )*TSTR + col]     = acc[mt][nt][0] + bv.x;
            tile[(r  )*TSTR + col + 1] = acc[mt][nt][1] + bv.y;
            tile[(r+8)*TSTR + col]     = acc[mt][nt][2] + bv.x;
            tile[(r+8)*TSTR + col + 1] = acc[mt][nt][3] + bv.y;
        }
    }
    __syncthreads();

    const int bb    = bm >> 11;
    const int sbase = bm & 2047;

    if (bn < DMODEL) {
        const int h = bn >> 7;
        __half* dst = Qo + ((size_t)(bb*NHEADS + h))*SEQ*HDIM;
        const float scale = 0.08838834764831845f;    // 1/sqrt(128)
        for (int r = wid; r < 128; r += 8) {
            int s = sbase + r;
            int pos = seq_pos[bb*SEQ + s];
            __half* d = dst + (size_t)s*HDIM;
            #pragma unroll
            for (int ii = 0; ii < 2; ii++) {
                int i = lane + ii*32;
                float2 sc = rope[pos*64 + i];
                float x1 = tile[r*TSTR + i], x2 = tile[r*TSTR + i + 64];
                d[i]      = __float2half_rn((x1*sc.y - x2*sc.x) * scale);
                d[i + 64] = __float2half_rn((x2*sc.y + x1*sc.x) * scale);
            }
        }
    } else {
        const int off = bn - DMODEL;
        const int kv  = off >> 8;
        if (((off >> 7) & 1) == 0) {
            __half* dst = Ko + ((size_t)(bb*NKV + kv))*SEQ*HDIM;
            for (int r = wid; r < 128; r += 8) {
                int s = sbase + r;
                int pos = seq_pos[bb*SEQ + s];
                __half* d = dst + (size_t)s*HDIM;
                #pragma unroll
                for (int ii = 0; ii < 2; ii++) {
                    int i = lane + ii*32;
                    float2 sc = rope[pos*64 + i];
                    float x1 = tile[r*TSTR + i], x2 = tile[r*TSTR + i + 64];
                    d[i]      = __float2half_rn(x1*sc.y - x2*sc.x);
                    d[i + 64] = __float2half_rn(x2*sc.y + x1*sc.x);
                }
            }
        } else {
            __half* dst = Vt + ((size_t)(bb*NKV + kv))*HDIM*SEQ;
            #pragma unroll
            for (int ci = 0; ci < 16; ci++) {
                int c = wid*16 + ci;
                __half* dc = dst + (size_t)c*SEQ + sbase;
                #pragma unroll
                for (int rr = 0; rr < 4; rr++) {
                    int r = lane + rr*32;
                    dc[r] = __float2half_rn(tile[r*TSTR + c]);
                }
            }
        }
    }
}

// ---------------------------------------------------------------------------
// O-projection GEMM
// ---------------------------------------------------------------------------
__global__ __launch_bounds__(256, 2) void gemm_f16(
    const __half* __restrict__ A, const __half* __restrict__ B,
    const float* __restrict__ bias, float* __restrict__ C,
    int M, int N, int K)
{
    extern __shared__ __half sh[];
    const int tid  = threadIdx.x;
    const int lane = tid & 31, wid = tid >> 5;
    const int wr   = wid >> 2, wc = wid & 3;
    const int gr   = lane >> 2, qd = lane & 3;
    const int bm   = blockIdx.y*128, bn = blockIdx.x*128;

    float acc[4][4][4];
    #pragma unroll
    for (int i = 0; i < 4; i++)
        #pragma unroll
        for (int j = 0; j < 4; j++)
            #pragma unroll
            for (int r = 0; r < 4; r++) acc[i][j][r] = 0.f;

    GEMM_MAINLOOP()

    #pragma unroll
    for (int nt = 0; nt < 4; nt++) {
        int col = bn + wc*32 + nt*8 + 2*qd;
        float2 bv = *(const float2*)(bias + col);
        #pragma unroll
        for (int mt = 0; mt < 4; mt++) {
            int row = bm + wr*64 + mt*16 + gr;
            *(float2*)(C + (size_t)row*N + col) =
                make_float2(acc[mt][nt][0] + bv.x, acc[mt][nt][1] + bv.y);
            *(float2*)(C + (size_t)(row + 8)*N + col) =
                make_float2(acc[mt][nt][2] + bv.x, acc[mt][nt][3] + bv.y);
        }
    }
}

// ---------------------------------------------------------------------------
// Flash attention: 128 thr = 4 warps, warp owns 16 rows; Q/P in regs;
// K/V fragment loads via ldmatrix; occ 3.
// ---------------------------------------------------------------------------
#define QS 136
#define VS 72
#define SMH_K0  0
#define SMH_K1  (64*QS)
#define SMH_V0  (2*64*QS)
#define SMH_V1  (2*64*QS + 128*VS)
#define FLASH_SMEM ((2*64*QS + 2*128*VS)*2)   // 71680 B

__global__ __launch_bounds__(128, 3) void flash_f16(
    const __half* __restrict__ Q, const __half* __restrict__ Kg,
    const __half* __restrict__ Vtg, __half* __restrict__ X)
{
    extern __shared__ __half smh[];

    const int qt  = 31 - blockIdx.x;
    const int h   = blockIdx.y;
    const int b   = blockIdx.z;
    const int kvh = h >> 2;
    const int q0  = qt * 64;

    const int tid  = threadIdx.x;
    const int lane = tid & 31, wid = tid >> 5;
    const int gr   = lane >> 2, qd = lane & 3;
    const int r0   = wid*16 + gr, r1 = r0 + 8;

    const __half* qb  = Q   + ((size_t)(b*NHEADS + h)*SEQ + q0)*HDIM;
    const __half* kb  = Kg  + (size_t)(b*NKV + kvh)*SEQ*HDIM;
    const __half* vtb = Vtg + (size_t)(b*NKV + kvh)*HDIM*SEQ;

    const uint32_t smb = (uint32_t)__cvta_generic_to_shared(smh);
    const int rowF = (lane & 7) + ((lane >> 4) << 3);
    const int colF = ((lane >> 3) & 1)*8;

    uint32_t qa[8][4];
    #pragma unroll
    for (int ks = 0; ks < 8; ks++) {
        qa[ks][0] = *(const uint32_t*)(qb + (size_t)r0*HDIM + ks*16     + 2*qd);
        qa[ks][1] = *(const uint32_t*)(qb + (size_t)r1*HDIM + ks*16     + 2*qd);
        qa[ks][2] = *(const uint32_t*)(qb + (size_t)r0*HDIM + ks*16 + 8 + 2*qd);
        qa[ks][3] = *(const uint32_t*)(qb + (size_t)r1*HDIM + ks*16 + 8 + 2*qd);
    }

    auto load_kv = [&](int buf, int kt) {
        __half* Ks = smh + (buf ? SMH_K1 : SMH_K0);
        __half* Vs = smh + (buf ? SMH_V1 : SMH_V0);
        const __half* kp = kb + (size_t)kt*64*HDIM;
        #pragma unroll
        for (int i = 0; i < 8; i++) {
            int slot = tid + i*128;
            int r = slot >> 4, c8 = (slot & 15)*8;
            cpa16(Ks + r*QS + c8, kp + r*HDIM + c8);
        }
        #pragma unroll
        for (int i = 0; i < 8; i++) {
            int slot = tid + i*128;
            int d = slot >> 3, c8 = (slot & 7)*8;
            cpa16(Vs + d*VS + c8, vtb + (size_t)d*SEQ + kt*64 + c8);
        }
        cp_commit();
    };

    load_kv(0, 0);

    float o[16][4];
    #pragma unroll
    for (int i = 0; i < 16; i++)
        #pragma unroll
        for (int j = 0; j < 4; j++) o[i][j] = 0.f;
    float m0 = -INFINITY, m1 = -INFINITY, l0 = 0.f, l1 = 0.f;

    for (int kt = 0; kt <= qt; kt++) {
        const int buf = kt & 1;
        __syncthreads();
        if (kt < qt) { load_kv(buf ^ 1, kt + 1); cp_wait1(); }
        else         { cp_wait0(); }
        __syncthreads();

        const uint32_t kBase = smb + ((buf ? SMH_K1 : SMH_K0) + rowF*QS + colF)*2;
        const uint32_t vBase = smb + ((buf ? SMH_V1 : SMH_V0) + rowF*VS + colF)*2;

        float s[8][4];
        #pragma unroll
        for (int nt = 0; nt < 8; nt++)
            #pragma unroll
            for (int j = 0; j < 4; j++) s[nt][j] = 0.f;

        #pragma unroll
        for (int ks = 0; ks < 8; ks++) {
            #pragma unroll
            for (int p = 0; p < 4; p++) {
                uint32_t bf[4];
                ldsm_x4(bf, kBase + (p*16*QS + ks*16)*2);
                mma_f16(s[2*p],     qa[ks], bf);
                mma_f16(s[2*p + 1], qa[ks], bf + 2);
            }
        }

        if (kt == qt) {
            #pragma unroll
            for (int nt = 0; nt < 8; nt++) {
                int cg = kt*64 + nt*8 + 2*qd;
                if (cg     > q0 + r0) s[nt][0] = -1e30f;
                if (cg + 1 > q0 + r0) s[nt][1] = -1e30f;
                if (cg     > q0 + r1) s[nt][2] = -1e30f;
                if (cg + 1 > q0 + r1) s[nt][3] = -1e30f;
            }
        }

        float mx0 = -INFINITY, mx1 = -INFINITY;
        #pragma unroll
        for (int nt = 0; nt < 8; nt++) {
            mx0 = fmaxf(mx0, fmaxf(s[nt][0], s[nt][1]));
            mx1 = fmaxf(mx1, fmaxf(s[nt][2], s[nt][3]));
        }
        mx0 = fmaxf(mx0, __shfl_xor_sync(0xffffffffu, mx0, 1));
        mx0 = fmaxf(mx0, __shfl_xor_sync(0xffffffffu, mx0, 2));
        mx1 = fmaxf(mx1, __shfl_xor_sync(0xffffffffu, mx1, 1));
        mx1 = fmaxf(mx1, __shfl_xor_sync(0xffffffffu, mx1, 2));
        float nm0 = fmaxf(m0, mx0), nm1 = fmaxf(m1, mx1);
        float corr0 = __expf(m0 - nm0), corr1 = __expf(m1 - nm1);

        uint32_t ph[8], pl[8];
        float sum0 = 0.f, sum1 = 0.f;
        #pragma unroll
        for (int nt = 0; nt < 8; nt++) {
            float p00 = __expf(s[nt][0] - nm0);
            float p01 = __expf(s[nt][1] - nm0);
            float p10 = __expf(s[nt][2] - nm1);
            float p11 = __expf(s[nt][3] - nm1);
            sum0 += p00 + p01; sum1 += p10 + p11;
            ph[nt] = packh2(p00, p01);
            pl[nt] = packh2(p10, p11);
        }
        sum0 += __shfl_xor_sync(0xffffffffu, sum0, 1);
        sum0 += __shfl_xor_sync(0xffffffffu, sum0, 2);
        sum1 += __shfl_xor_sync(0xffffffffu, sum1, 1);
        sum1 += __shfl_xor_sync(0xffffffffu, sum1, 2);
        l0 = l0*corr0 + sum0;
        l1 = l1*corr1 + sum1;
        m0 = nm0; m1 = nm1;

        #pragma unroll
        for (int nt = 0; nt < 16; nt++) {
            o[nt][0] *= corr0; o[nt][1] *= corr0;
            o[nt][2] *= corr1; o[nt][3] *= corr1;
        }

        #pragma unroll
        for (int t = 0; t < 4; t++) {
            uint32_t a[4] = { ph[2*t], pl[2*t], ph[2*t + 1], pl[2*t + 1] };
            #pragma unroll
            for (int p = 0; p < 8; p++) {
                uint32_t bf[4];
                ldsm_x4(bf, vBase + (p*16*VS + t*16)*2);
                mma_f16(o[2*p],     a, bf);
                mma_f16(o[2*p + 1], a, bf + 2);
            }
        }
    }

    float inv0 = 1.f / l0, inv1 = 1.f / l1;
    size_t rb0 = ((size_t)(b*SEQ + q0 + r0))*DMODEL + h*HDIM;
    size_t rb1 = ((size_t)(b*SEQ + q0 + r1))*DMODEL + h*HDIM;
    #pragma unroll
    for (int nt = 0; nt < 16; nt++) {
        int cc = nt*8 + 2*qd;
        *(__half2*)(X + rb0 + cc) = __floats2half2_rn(o[nt][0]*inv0, o[nt][1]*inv0);
        *(__half2*)(X + rb1 + cc) = __floats2half2_rn(o[nt][2]*inv1, o[nt][3]*inv1);
    }
}

// ---------------------------------------------------------------------------
// Launch
// ---------------------------------------------------------------------------
extern "C" void kernel_launch(void* const* d_in, const int* in_sizes, int n_in,
                              void* d_out, int out_size)
{
    const float* inputs  = (const float*)d_in[0];
    const int*   seq_pos = (const int*)  d_in[1];
    const float* wq      = (const float*)d_in[2];
    const float* bq      = (const float*)d_in[3];
    const float* wkv     = (const float*)d_in[4];
    const float* bkv     = (const float*)d_in[5];
    const float* wo      = (const float*)d_in[6];
    const float* bo      = (const float*)d_in[7];
    float* out = (float*)d_out;

    __half *in_h, *wqkv_h, *wo_h, *x_h, *q, *k, *vt;
    float2* rope;
    cudaGetSymbolAddress((void**)&in_h,   g_in_h);
    cudaGetSymbolAddress((void**)&wqkv_h, g_wqkv_h);
    cudaGetSymbolAddress((void**)&wo_h,   g_wo_h);
    cudaGetSymbolAddress((void**)&x_h,    g_x_h);
    cudaGetSymbolAddress((void**)&q,      g_q);
    cudaGetSymbolAddress((void**)&k,      g_k);
    cudaGetSymbolAddress((void**)&vt,     g_vt);
    cudaGetSymbolAddress((void**)&rope,   g_rope);

    const int GEMM_SMEM = 2*HBUF*2;     // 73728 B
    cudaFuncSetAttribute(gemm_qkv,
                         cudaFuncAttributeMaxDynamicSharedMemorySize, GEMM_SMEM);
    cudaFuncSetAttribute(gemm_f16,
                         cudaFuncAttributeMaxDynamicSharedMemorySize, GEMM_SMEM);
    cudaFuncSetAttribute(flash_f16,
                         cudaFuncAttributeMaxDynamicSharedMemorySize, FLASH_SMEM);

    // 0) merged staging (wide cvt stores)
    staging<<<STG_TOT, 256>>>((const float4*)inputs, wq, wkv, wo,
                              (uint4*)in_h, wqkv_h, wo_h, rope);

    // 1) fused QKV projection + rope + V transpose
    gemm_qkv<<<dim3(NQKV/128, M_TOK/128), 256, GEMM_SMEM>>>(
        in_h, wqkv_h, bq, bkv, seq_pos, rope, q, k, vt);

    // 2) flash attention
    flash_f16<<<dim3(SEQ/64, NHEADS, BATCH), 128, FLASH_SMEM>>>(q, k, vt, x_h);

    // 3) output projection
    gemm_f16<<<dim3(DMODEL/128, M_TOK/128), 256, GEMM_SMEM>>>(
        x_h, wo_h, bo, out, M_TOK, DMODEL, DMODEL);
}